// round 15
// baseline (speedup 1.0000x reference)
#include <cuda_runtime.h>
#include <cuda_fp16.h>
#include <math.h>
#include <stdint.h>

#define T_TOK 1024
#define H_DIM 2048
#define E_NUM 32
#define I_DIM 768
#define I2    1536
#define TOPK  8
#define NGROUP 4
#define GSIZE  8
#define TOPKG  2
#define RSCALE 2.5f
#define IH     (I_DIM / 2)
#define XH     (H_DIM / 2)

// ---------------- scratch -------------------------------------------------
__device__ int   g_count[E_NUM];
__device__ int   g_offset[E_NUM];
__device__ int   g_cursor[E_NUM];
__device__ int   g_pair_token[T_TOK * TOPK];
__device__ float g_pair_w[T_TOK * TOPK];
__device__ int   g_tid_ids[T_TOK * TOPK];
__device__ float g_tid_w[T_TOK * TOPK];
__device__ __align__(16) uint32_t g_xh[(size_t)T_TOK * XH];
__device__ __align__(16) uint32_t g_act[(size_t)T_TOK * TOPK * IH];
__device__ __align__(16) uint32_t g_act_sh[(size_t)T_TOK * IH];

// ---------------- helpers -------------------------------------------------
__device__ __forceinline__ uint32_t pack2h(float v0, float v1) {
    uint32_t r;
    asm("cvt.rn.f16x2.f32 %0, %1, %2;" : "=r"(r) : "f"(v1), "f"(v0));
    return r;
}
__device__ __forceinline__ uint32_t s2u(const void* p) {
    uint32_t a;
    asm("{ .reg .u64 t; cvta.to.shared.u64 t, %1; cvt.u32.u64 %0, t; }" : "=r"(a) : "l"(p));
    return a;
}
__device__ __forceinline__ void ldm4(uint32_t* d, uint32_t addr) {
    asm volatile("ldmatrix.sync.aligned.m8n8.x4.shared.b16 {%0,%1,%2,%3}, [%4];"
                 : "=r"(d[0]), "=r"(d[1]), "=r"(d[2]), "=r"(d[3]) : "r"(addr));
}
__device__ __forceinline__ void ldm4t(uint32_t* d, uint32_t addr) {
    asm volatile("ldmatrix.sync.aligned.m8n8.x4.trans.shared.b16 {%0,%1,%2,%3}, [%4];"
                 : "=r"(d[0]), "=r"(d[1]), "=r"(d[2]), "=r"(d[3]) : "r"(addr));
}
__device__ __forceinline__ void mmah(float* c,
                                     uint32_t a0, uint32_t a1, uint32_t a2, uint32_t a3,
                                     uint32_t b0, uint32_t b1) {
    asm volatile("mma.sync.aligned.m16n8k16.row.col.f32.f16.f16.f32 "
                 "{%0,%1,%2,%3}, {%4,%5,%6,%7}, {%8,%9}, {%0,%1,%2,%3};"
                 : "+f"(c[0]), "+f"(c[1]), "+f"(c[2]), "+f"(c[3])
                 : "r"(a0), "r"(a1), "r"(a2), "r"(a3), "r"(b0), "r"(b1));
}
__device__ __forceinline__ void red2(float* addr, float v0, float v1) {
    asm volatile("red.global.add.v2.f32 [%0], {%1, %2};"
                 :: "l"(addr), "f"(v0), "f"(v1) : "memory");
}
#define CPA16(dst, src) asm volatile("cp.async.cg.shared.global [%0], [%1], 16;" :: "r"(dst), "l"(src))
#define CPA_COMMIT()    asm volatile("cp.async.commit_group;" ::: "memory")
#define CPA_WAIT0()     asm volatile("cp.async.wait_group 0;" ::: "memory")
__device__ __forceinline__ float silu(float x) { return x / (1.f + expf(-x)); }

// ---------------- prep: zero out + init counters + X -> fp16 --------------
__global__ void prep_kernel(const float2* __restrict__ x, float4* __restrict__ out) {
    int idx = blockIdx.x * 256 + threadIdx.x;
    if (idx < T_TOK * XH) {
        float2 v = x[idx];
        g_xh[idx] = pack2h(v.x, v.y);
    }
    if (idx < T_TOK * H_DIM / 4) out[idx] = make_float4(0.f, 0.f, 0.f, 0.f);
    if (idx < E_NUM) { g_count[idx] = 0; g_cursor[idx] = 0; g_offset[idx] = 0; }
}

// ---------------- routing (proven) ----------------------------------------
__global__ void routing_kernel(const float* __restrict__ x,
                               const float* __restrict__ gw,
                               const float* __restrict__ gbias) {
    int t = blockIdx.x;
    __shared__ float xs[H_DIM];
    __shared__ float sc[E_NUM];
    __shared__ float scc[E_NUM];
    int tid = threadIdx.x;
    for (int h = tid; h < H_DIM; h += 256) xs[h] = x[(size_t)t * H_DIM + h];
    __syncthreads();
    int warp = tid >> 5, lane = tid & 31;
    for (int e = warp; e < E_NUM; e += 8) {
        const float* wrow = gw + (size_t)e * H_DIM;
        float s = 0.f;
        for (int h = lane; h < H_DIM; h += 32) s += xs[h] * wrow[h];
        #pragma unroll
        for (int o = 16; o > 0; o >>= 1) s += __shfl_xor_sync(0xffffffffu, s, o);
        if (lane == 0) {
            float sg = 1.f / (1.f + expf(-s));
            sc[e] = sg;
            scc[e] = sg + gbias[e];
        }
    }
    __syncthreads();
    if (tid == 0) {
        float gsc[NGROUP];
        #pragma unroll
        for (int g = 0; g < NGROUP; g++) {
            float m1 = -1e30f, m2 = -1e30f;
            for (int j = 0; j < GSIZE; j++) {
                float v = scc[g * GSIZE + j];
                if (v > m1) { m2 = m1; m1 = v; }
                else if (v > m2) { m2 = v; }
            }
            gsc[g] = m1 + m2;
        }
        bool gm[NGROUP] = {false, false, false, false};
        {
            float tg[NGROUP];
            #pragma unroll
            for (int g = 0; g < NGROUP; g++) tg[g] = gsc[g];
            for (int k = 0; k < TOPKG; k++) {
                int bi = 0; float bv = tg[0];
                for (int g = 1; g < NGROUP; g++) if (tg[g] > bv) { bv = tg[g]; bi = g; }
                gm[bi] = true; tg[bi] = -1e30f;
            }
        }
        float tmp[E_NUM];
        for (int e = 0; e < E_NUM; e++) tmp[e] = gm[e / GSIZE] ? scc[e] : 0.0f;
        int ids[TOPK]; float ws[TOPK]; float wsum = 0.f;
        for (int k = 0; k < TOPK; k++) {
            int bi = 0; float bv = tmp[0];
            for (int e = 1; e < E_NUM; e++) if (tmp[e] > bv) { bv = tmp[e]; bi = e; }
            ids[k] = bi; tmp[bi] = -1e30f;
            ws[k] = sc[bi]; wsum += ws[k];
        }
        float inv = 1.f / wsum;
        for (int k = 0; k < TOPK; k++) {
            g_tid_ids[t * TOPK + k] = ids[k];
            g_tid_w[t * TOPK + k] = ws[k] * inv;
            atomicAdd(&g_count[ids[k]], 1);
        }
    }
}

// ---------------- scan + fill (single block) -------------------------------
__global__ void scanfill_kernel() {
    int tid = threadIdx.x;
    if (tid == 0) {
        int acc = 0;
        for (int e = 0; e < E_NUM; e++) {
            g_offset[e] = acc; g_cursor[e] = acc; acc += g_count[e];
        }
    }
    __syncthreads();
    for (int i = tid; i < T_TOK * TOPK; i += 1024) {
        int e = g_tid_ids[i];
        int pos = atomicAdd(&g_cursor[e], 1);
        g_pair_token[pos] = i / TOPK;
        g_pair_w[pos]     = g_tid_w[i];
    }
}

// ============================================================================
// GEMM 1: Xh @ W[gate|up] -> act(fp16), SiLU*mul. BM=128, BN=64(+64), BK=32.
// SMEM slot: A[128 x 20u], Bg[32 x 36u], Bu[32 x 36u]. cp.async A, LDG.128 B.
// ============================================================================
#define SA1 20
#define SB1 36
#define A1_SZ (128 * SA1)                 // 2560 uints
#define B1_SZ (32 * SB1)                  // 1152 uints
#define SLOT1 (A1_SZ + 2 * B1_SZ)         // 4864 uints
#define G1_SMEM (3 * SLOT1 * 4)           // 58368 B

__global__ __launch_bounds__(256, 2)
void mma_gateup_kernel(const float* __restrict__ Wgu,
                       const float* __restrict__ Sgu) {
    extern __shared__ uint32_t smu[];
    const int e = blockIdx.z;
    const bool routed = (e < E_NUM);
    const int M = routed ? g_count[e] : T_TOK;
    const int m0 = blockIdx.y * 128;
    if (m0 >= M) return;
    const int n0 = blockIdx.x * 64;
    const float* W = routed ? (Wgu + (size_t)e * H_DIM * I2) : Sgu;
    const int off = routed ? g_offset[e] : 0;
    uint32_t* act = routed ? (g_act + (size_t)off * IH) : g_act_sh;

    const int tid = threadIdx.x;
    const int lane = tid & 31, wid = tid >> 5;
    const int g = lane >> 2, tg = lane & 3;
    const int wm = (wid >> 1) * 32, wn = (wid & 1) * 32;
    const uint32_t smb = s2u(smu);

    // A cp.async mapping
    const int arow_i = tid >> 1, au4 = tid & 1;
    int ar = m0 + arow_i;
    int tokr = (ar < M) ? ar : m0;
    if (routed) tokr = g_pair_token[off + tokr];
    const char* Asrc = (const char*)(g_xh + (size_t)tokr * XH);
    const uint32_t adst = (uint32_t)((arow_i * SA1 + au4 * 4) * 4);

    // B fill mapping: mat | 8 k-rows | 16 n4-groups
    const int bmat = tid >> 7;
    const int bt = tid & 127;
    const int bn4 = (bt & 15) * 4;
    const int bkr = bt >> 4;                       // 0..7
    const float* Bsrc = W + n0 + bmat * I_DIM;

    // ldmatrix offsets
    const int lrow = lane & 15, lchunk = (lane >> 4) * 16;
    const int brow_l = (lane & 7) + ((lane >> 3) & 1) * 8;
    const int jsel = lane >> 4;
    uint32_t aoff[2], bgoff[2];
    #pragma unroll
    for (int mt = 0; mt < 2; mt++)
        aoff[mt] = (uint32_t)((wm + mt * 16 + lrow) * SA1 * 4 + lchunk);
    #pragma unroll
    for (int p = 0; p < 2; p++)
        bgoff[p] = (uint32_t)(A1_SZ * 4 + brow_l * SB1 * 4 + ((wn >> 3) + 2 * p + jsel) * 16);

    float cg[2][4][4], cu[2][4][4];
    #pragma unroll
    for (int a = 0; a < 2; a++)
        #pragma unroll
        for (int b = 0; b < 4; b++)
            #pragma unroll
            for (int c = 0; c < 4; c++) { cg[a][b][c] = 0.f; cu[a][b][c] = 0.f; }

    float4 pb[4];
    const int NK = H_DIM / 32;   // 64

    // prologue: B(0)->regs->slot0, A(0) cp.async->slot0, B(1)->regs
    #pragma unroll
    for (int b = 0; b < 4; b++)
        pb[b] = *(const float4*)(Bsrc + (size_t)(bkr + 8 * b) * I2 + bn4);
    {
        uint32_t* Bq = smu + A1_SZ + bmat * B1_SZ;
        #pragma unroll
        for (int b = 0; b < 4; b++) {
            int row = bkr + 8 * b;
            uint2 v = make_uint2(pack2h(pb[b].x, pb[b].y), pack2h(pb[b].z, pb[b].w));
            *(uint2*)&Bq[row * SB1 + bn4 / 2] = v;
        }
        CPA16(smb + adst, Asrc + au4 * 16);
        CPA16(smb + adst + 32, Asrc + au4 * 16 + 32);
    }
    CPA_COMMIT();
    #pragma unroll
    for (int b = 0; b < 4; b++)
        pb[b] = *(const float4*)(Bsrc + (size_t)(32 + bkr + 8 * b) * I2 + bn4);

    int slot_c = 0;
    for (int kt = 0; kt < NK; kt++) {
        CPA_WAIT0();
        __syncthreads();
        int slot_s = slot_c + 1; if (slot_s == 3) slot_s = 0;
        if (kt + 1 < NK) {
            uint32_t* Bq = smu + slot_s * SLOT1 + A1_SZ + bmat * B1_SZ;
            #pragma unroll
            for (int b = 0; b < 4; b++) {
                int row = bkr + 8 * b;
                uint2 v = make_uint2(pack2h(pb[b].x, pb[b].y), pack2h(pb[b].z, pb[b].w));
                *(uint2*)&Bq[row * SB1 + bn4 / 2] = v;
            }
            uint32_t d0 = smb + (uint32_t)(slot_s * SLOT1 * 4) + adst;
            const char* s0 = Asrc + ((size_t)(kt + 1) * 4 + au4) * 16;
            CPA16(d0, s0);
            CPA16(d0 + 32, s0 + 32);
        }
        CPA_COMMIT();
        if (kt + 2 < NK) {
            const float* bp = Bsrc + (size_t)(kt + 2) * 32 * I2;
            #pragma unroll
            for (int b = 0; b < 4; b++)
                pb[b] = *(const float4*)(bp + (size_t)(bkr + 8 * b) * I2 + bn4);
        }
        {
            const uint32_t sb = smb + (uint32_t)(slot_c * SLOT1 * 4);
            #pragma unroll
            for (int kk = 0; kk < 2; kk++) {
                uint32_t a[2][4], bg[2][4], bu[2][4];
                #pragma unroll
                for (int mt = 0; mt < 2; mt++) ldm4(a[mt], sb + aoff[mt] + kk * 32);
                #pragma unroll
                for (int p = 0; p < 2; p++) {
                    ldm4t(bg[p], sb + bgoff[p] + kk * (16 * SB1 * 4));
                    ldm4t(bu[p], sb + bgoff[p] + B1_SZ * 4 + kk * (16 * SB1 * 4));
                }
                #pragma unroll
                for (int p = 0; p < 2; p++)
                    #pragma unroll
                    for (int s = 0; s < 2; s++) {
                        const int nt = p * 2 + s;
                        uint32_t g0 = bg[p][2 * s], g1 = bg[p][2 * s + 1];
                        uint32_t u0 = bu[p][2 * s], u1 = bu[p][2 * s + 1];
                        #pragma unroll
                        for (int mt = 0; mt < 2; mt++) {
                            mmah(cg[mt][nt], a[mt][0], a[mt][1], a[mt][2], a[mt][3], g0, g1);
                            mmah(cu[mt][nt], a[mt][0], a[mt][1], a[mt][2], a[mt][3], u0, u1);
                        }
                    }
            }
        }
        slot_c = slot_s;
    }

    // epilogue: SiLU(gate)*up -> act (fp16x2)
    #pragma unroll
    for (int mt = 0; mt < 2; mt++) {
        const int r1 = m0 + wm + mt * 16 + g;
        const int r2 = r1 + 8;
        #pragma unroll
        for (int nt = 0; nt < 4; nt++) {
            const int col = n0 + wn + nt * 8 + 2 * tg;
            if (r1 < M)
                act[(size_t)r1 * IH + col / 2] =
                    pack2h(silu(cg[mt][nt][0]) * cu[mt][nt][0],
                           silu(cg[mt][nt][1]) * cu[mt][nt][1]);
            if (r2 < M)
                act[(size_t)r2 * IH + col / 2] =
                    pack2h(silu(cg[mt][nt][2]) * cu[mt][nt][2],
                           silu(cg[mt][nt][3]) * cu[mt][nt][3]);
        }
    }
}

// ============================================================================
// GEMM 2: act(fp16) @ Wd -> v2-RED combine. BM=128, BN=128, BK=32.
// SMEM slot: A[128 x 20u], B[32 x 68u]. cp.async A, LDG.128 B, ldmatrix.trans.
// ============================================================================
#define SB2 68
#define A2_SZ (128 * SA1)                 // 2560
#define B2_SZ (32 * SB2)                  // 2176
#define SLOT2 (A2_SZ + B2_SZ)             // 4736
#define G2_SMEM (3 * SLOT2 * 4)           // 56832 B

__global__ __launch_bounds__(256, 2)
void mma_down_kernel(const float* __restrict__ Wd,
                     const float* __restrict__ Sd,
                     float* __restrict__ out) {
    extern __shared__ uint32_t smu[];
    const int e = blockIdx.z;
    const bool routed = (e < E_NUM);
    const int M = routed ? g_count[e] : T_TOK;
    const int m0 = blockIdx.y * 128;
    if (m0 >= M) return;
    const int n0 = blockIdx.x * 128;
    const float* W = routed ? (Wd + (size_t)e * I_DIM * H_DIM) : Sd;
    const int off = routed ? g_offset[e] : 0;
    const uint32_t* A = routed ? (g_act + (size_t)off * IH) : g_act_sh;

    const int tid = threadIdx.x;
    const int lane = tid & 31, wid = tid >> 5;
    const int g = lane >> 2, tg = lane & 3;
    const int wm = (wid >> 1) * 32, wn = (wid & 1) * 64;
    const uint32_t smb = s2u(smu);

    const int arow_i = tid >> 1, au4 = tid & 1;
    int ar = m0 + arow_i;
    const char* Asrc = (const char*)(A + (size_t)((ar < M) ? ar : m0) * IH);
    const uint32_t adst = (uint32_t)((arow_i * SA1 + au4 * 4) * 4);

    const int bn4 = (tid & 31) * 4;
    const int bkr = tid >> 5;                  // 0..7
    const float* Bsrc = W + n0;

    const int lrow = lane & 15, lchunk = (lane >> 4) * 16;
    const int brow_l = (lane & 7) + ((lane >> 3) & 1) * 8;
    const int jsel = lane >> 4;
    uint32_t aoff[2], boff[4];
    #pragma unroll
    for (int mt = 0; mt < 2; mt++)
        aoff[mt] = (uint32_t)((wm + mt * 16 + lrow) * SA1 * 4 + lchunk);
    #pragma unroll
    for (int p = 0; p < 4; p++)
        boff[p] = (uint32_t)(A2_SZ * 4 + brow_l * SB2 * 4 + ((wn >> 3) + 2 * p + jsel) * 16);

    float cc[2][8][4];
    #pragma unroll
    for (int a = 0; a < 2; a++)
        #pragma unroll
        for (int b = 0; b < 8; b++)
            #pragma unroll
            for (int c = 0; c < 4; c++) cc[a][b][c] = 0.f;

    float4 pb[4];
    const int NK = I_DIM / 32;    // 24

    #pragma unroll
    for (int b = 0; b < 4; b++)
        pb[b] = *(const float4*)(Bsrc + (size_t)(bkr + 8 * b) * H_DIM + bn4);
    {
        uint32_t* Bq = smu + A2_SZ;
        #pragma unroll
        for (int b = 0; b < 4; b++) {
            int row = bkr + 8 * b;
            uint2 v = make_uint2(pack2h(pb[b].x, pb[b].y), pack2h(pb[b].z, pb[b].w));
            *(uint2*)&Bq[row * SB2 + bn4 / 2] = v;
        }
        CPA16(smb + adst, Asrc + au4 * 16);
        CPA16(smb + adst + 32, Asrc + au4 * 16 + 32);
    }
    CPA_COMMIT();
    #pragma unroll
    for (int b = 0; b < 4; b++)
        pb[b] = *(const float4*)(Bsrc + (size_t)(32 + bkr + 8 * b) * H_DIM + bn4);

    int slot_c = 0;
    for (int kt = 0; kt < NK; kt++) {
        CPA_WAIT0();
        __syncthreads();
        int slot_s = slot_c + 1; if (slot_s == 3) slot_s = 0;
        if (kt + 1 < NK) {
            uint32_t* Bq = smu + slot_s * SLOT2 + A2_SZ;
            #pragma unroll
            for (int b = 0; b < 4; b++) {
                int row = bkr + 8 * b;
                uint2 v = make_uint2(pack2h(pb[b].x, pb[b].y), pack2h(pb[b].z, pb[b].w));
                *(uint2*)&Bq[row * SB2 + bn4 / 2] = v;
            }
            uint32_t d0 = smb + (uint32_t)(slot_s * SLOT2 * 4) + adst;
            const char* s0 = Asrc + ((size_t)(kt + 1) * 4 + au4) * 16;
            CPA16(d0, s0);
            CPA16(d0 + 32, s0 + 32);
        }
        CPA_COMMIT();
        if (kt + 2 < NK) {
            const float* bp = Bsrc + (size_t)(kt + 2) * 32 * H_DIM;
            #pragma unroll
            for (int b = 0; b < 4; b++)
                pb[b] = *(const float4*)(bp + (size_t)(bkr + 8 * b) * H_DIM + bn4);
        }
        {
            const uint32_t sb = smb + (uint32_t)(slot_c * SLOT2 * 4);
            #pragma unroll
            for (int kk = 0; kk < 2; kk++) {
                uint32_t a[2][4], bb[4][4];
                #pragma unroll
                for (int mt = 0; mt < 2; mt++) ldm4(a[mt], sb + aoff[mt] + kk * 32);
                #pragma unroll
                for (int p = 0; p < 4; p++) ldm4t(bb[p], sb + boff[p] + kk * (16 * SB2 * 4));
                #pragma unroll
                for (int p = 0; p < 4; p++)
                    #pragma unroll
                    for (int s = 0; s < 2; s++) {
                        const int nt = p * 2 + s;
                        uint32_t b0 = bb[p][2 * s], b1 = bb[p][2 * s + 1];
                        #pragma unroll
                        for (int mt = 0; mt < 2; mt++)
                            mmah(cc[mt][nt], a[mt][0], a[mt][1], a[mt][2], a[mt][3], b0, b1);
                    }
            }
        }
        slot_c = slot_s;
    }

    // epilogue: weighted combine via vector RED
    #pragma unroll
    for (int mt = 0; mt < 2; mt++) {
        const int r1 = m0 + wm + mt * 16 + g;
        const int r2 = r1 + 8;
        int tok1 = 0, tok2 = 0;
        float s1 = 0.f, s2 = 0.f;
        bool ok1 = (r1 < M), ok2 = (r2 < M);
        if (ok1) {
            if (routed) { tok1 = g_pair_token[off + r1]; s1 = g_pair_w[off + r1] * RSCALE; }
            else        { tok1 = r1; s1 = 1.0f; }
        }
        if (ok2) {
            if (routed) { tok2 = g_pair_token[off + r2]; s2 = g_pair_w[off + r2] * RSCALE; }
            else        { tok2 = r2; s2 = 1.0f; }
        }
        float* o1 = out + (size_t)tok1 * H_DIM;
        float* o2 = out + (size_t)tok2 * H_DIM;
        #pragma unroll
        for (int nt = 0; nt < 8; nt++) {
            const int col = n0 + wn + nt * 8 + 2 * tg;
            if (ok1) red2(o1 + col, cc[mt][nt][0] * s1, cc[mt][nt][1] * s1);
            if (ok2) red2(o2 + col, cc[mt][nt][2] * s2, cc[mt][nt][3] * s2);
        }
    }
}

// ---------------- launch ---------------------------------------------------
extern "C" void kernel_launch(void* const* d_in, const int* in_sizes, int n_in,
                              void* d_out, int out_size) {
    (void)in_sizes; (void)n_in; (void)out_size;
    const float* hidden    = (const float*)d_in[0];
    const float* gate_w    = (const float*)d_in[1];
    const float* gate_bias = (const float*)d_in[2];
    const float* w_gate_up = (const float*)d_in[3];
    const float* w_down    = (const float*)d_in[4];
    const float* s_gate_up = (const float*)d_in[5];
    const float* s_down    = (const float*)d_in[6];
    float* out = (float*)d_out;

    cudaFuncSetAttribute(mma_gateup_kernel, cudaFuncAttributeMaxDynamicSharedMemorySize, G1_SMEM);
    cudaFuncSetAttribute(mma_down_kernel,   cudaFuncAttributeMaxDynamicSharedMemorySize, G2_SMEM);

    prep_kernel<<<(T_TOK * XH + 255) / 256, 256>>>((const float2*)hidden, (float4*)out);
    routing_kernel<<<T_TOK, 256>>>(hidden, gate_w, gate_bias);
    scanfill_kernel<<<1, 1024>>>();

    {
        dim3 grid(I_DIM / 64, T_TOK / 128, E_NUM + 1);    // (12, 8, 33)
        mma_gateup_kernel<<<grid, 256, G1_SMEM>>>(w_gate_up, s_gate_up);
    }
    {
        dim3 grid(H_DIM / 128, T_TOK / 128, E_NUM + 1);   // (16, 8, 33)
        mma_down_kernel<<<grid, 256, G2_SMEM>>>(w_down, s_down, out);
    }
}